// round 9
// baseline (speedup 1.0000x reference)
#include <cuda_runtime.h>
#include <stdint.h>

// Problem constants (fixed by the dataset)
#define NBATCH 16
#define TT     2048
#define SS     2048
#define HH     64
#define KSEL   64

typedef unsigned long long ull;

__device__ __forceinline__ ull umax64(ull a, ull b) { return a > b ? a : b; }
__device__ __forceinline__ ull umin64(ull a, ull b) { return a < b ? a : b; }

// key = (sortable_score << 8) | (127 - expanded_idx)
// numeric DESC order == desc by score, ties broken by ascending index (lax.top_k)
__device__ __forceinline__ ull enc_key(float s, int idx) {
    unsigned int u  = __float_as_uint(s);
    unsigned int su = (u & 0x80000000u) ? ~u : (u | 0x80000000u);
    return ((ull)su << 8) | (ull)(127 - idx);
}

__device__ __forceinline__ float dec_score(ull key) {
    unsigned int su = (unsigned int)(key >> 8);
    unsigned int u  = (su & 0x80000000u) ? (su & 0x7FFFFFFFu) : ~su;
    return __uint_as_float(u);
}

__global__ __launch_bounds__(64)
void tree_attn_kernel(const float* __restrict__ q,
                      const float* __restrict__ kmat,
                      const float* __restrict__ v,
                      float* __restrict__ out)
{
    __shared__ float sc_odd[64];   // fresh (odd-child) scores
    __shared__ ull   xkey[64];     // key exchange / handoff
    __shared__ int   zpar[64];     // parent z values
    __shared__ int   pos_s[64];
    __shared__ float pvec[64];
    __shared__ float red[4];

    const int row  = blockIdx.x;
    const int n    = row >> 11;
    const int t    = row & (TT - 1);
    const float tsrc = (float)(t + 1);

    const int g    = threadIdx.x;   // 0..63
    const int lane = g & 31;
    const int l16  = g & 15;
    const int hwg  = g >> 4;        // half-warp 0..3

    const float* kbase = kmat + (size_t)n * SS * HH;
    const float4 q4 = ((const float4*)(q + ((size_t)(n * TT + t)) * HH))[l16];

    ull key = 0;                    // selection key (64 threads, it0/it1 phase)
    int zsel = 0;

    // R3-verbatim pinned scoring reduction tree. DO NOT change the order:
    // its rounding bit-matches the reference einsum, which the tie-break
    // replication (equal pos -> bit-equal score) depends on.
    #define SCORE_FRESH(POS, CIDX)                                            \
        {                                                                     \
            const float4* krow = (const float4*)(kbase + (size_t)(POS) * HH); \
            float4 k4 = krow[l16];                                            \
            float part = q4.x * k4.x + q4.y * k4.y + q4.z * k4.z + q4.w * k4.w;\
            part += __shfl_xor_sync(0xffffffffu, part, 1);                    \
            part += __shfl_xor_sync(0xffffffffu, part, 2);                    \
            part += __shfl_xor_sync(0xffffffffu, part, 4);                    \
            part += __shfl_xor_sync(0xffffffffu, part, 8);                    \
            if (l16 == 0) sc_odd[CIDX] = part;                                \
        }

    // ---------------- iteration 0: 32 fresh candidates, w2=32 ----------------
    {
        const float r = tsrc * (1.0f / 32.0f);
        for (int c = hwg; c < 32; c += 4) {
            int pos = min((int)rintf((float)c * r), SS - 1);
            SCORE_FRESH(pos, c)
        }
        __syncthreads();
        if (g < 32) {   // warp0: 15-stage desc bitonic sort of 32
            key = enc_key(sc_odd[lane], lane);   // expanded idx == z at level 0
            #pragma unroll
            for (int kk = 2; kk <= 32; kk <<= 1)
                #pragma unroll
                for (int j = kk >> 1; j > 0; j >>= 1) {
                    ull p = __shfl_xor_sync(0xffffffffu, key, j);
                    bool mx = (((lane & j) == 0) == ((lane & kk) == 0));
                    key = mx ? umax64(key, p) : umin64(key, p);
                }
            zsel = 127 - (int)(key & 0xFFu);
        }
        __syncthreads();   // sc_odd reuse barrier
    }

    // ---------------- iteration 1: 32 parents -> keep all 64, w2=64 ----------
    {
        if (g < 32) zpar[g] = zsel;
        __syncthreads();
        const float r = tsrc * (1.0f / 64.0f);
        for (int i = hwg; i < 32; i += 4) {
            int z = 2 * zpar[i] + 1;                       // odd child only
            int pos = min((int)rintf((float)z * r), SS - 1);
            SCORE_FRESH(pos, i)
        }
        __syncthreads();
        // warp0 sorts the 32 odd keys desc
        ull okey = 0;
        if (g < 32) {
            okey = enc_key(sc_odd[lane], 2 * lane + 1);
            #pragma unroll
            for (int kk = 2; kk <= 32; kk <<= 1)
                #pragma unroll
                for (int j = kk >> 1; j > 0; j >>= 1) {
                    ull p = __shfl_xor_sync(0xffffffffu, okey, j);
                    bool mx = (((lane & j) == 0) == ((lane & kk) == 0));
                    okey = mx ? umax64(okey, p) : umin64(okey, p);
                }
            xkey[lane] = okey;
            // even child keeps parent score; new expanded idx = 2g
            key = (key & ~0xFFull) | (ull)(127 - 2 * g);
        }
        __syncthreads();
        if (g >= 32) key = xkey[63 - g];   // reversed odds -> bitonic 64
        __syncthreads();
        // 6-stage desc merge over 64 (order defines next level's tie-breaks)
        #pragma unroll
        for (int j = 32; j > 0; j >>= 1) {
            ull p;
            if (j == 32) { xkey[g] = key; __syncthreads(); p = xkey[g ^ 32]; __syncthreads(); }
            else          p = __shfl_xor_sync(0xffffffffu, key, j);
            bool mx = ((g & j) == 0);
            key = mx ? umax64(key, p) : umin64(key, p);
        }
        int e = 127 - (int)(key & 0xFFu);
        zsel = 2 * zpar[e >> 1] + (e & 1);
    }

    // ---- handoff: sorted top-64 -> warp0, 2 elements/thread ------------------
    __syncthreads();               // zpar reuse (read above) before overwrite
    zpar[g] = zsel;
    xkey[g] = key;
    __syncthreads();

    ull E0 = 0, E1 = 0;            // warp0 state: sorted positions 2t, 2t+1
    const int tw = lane;
    if (g < 32) { E0 = xkey[2 * tw]; E1 = xkey[2 * tw + 1]; }

    // ---------------- iterations 2..6: warp0-resident selection ---------------
    // Any correct desc sort of the (unique) keys reproduces lax.top_k exactly,
    // so the network may differ from the reference path; only keys are pinned.
    #pragma unroll 1
    for (int it = 2; it < 7; ++it) {
        const float r = tsrc / (float)(32 << it);
        for (int i = hwg; i < 64; i += 4) {
            int z = 2 * zpar[i] + 1;                       // odd children fresh
            int pos = min((int)rintf((float)z * r), SS - 1);
            SCORE_FRESH(pos, i)
        }
        __syncthreads();

        if (g < 32) {
            // odd keys, 2/thread: p = 2t (O0), 2t+1 (O1); expanded idx 2p+1
            ull O0 = enc_key(sc_odd[2 * tw],     4 * tw + 1);
            ull O1 = enc_key(sc_odd[2 * tw + 1], 4 * tw + 3);

            // desc bitonic sort of 64, 2 elems/thread (j==1 stages local)
            #pragma unroll
            for (int kk = 2; kk <= 64; kk <<= 1) {
                #pragma unroll
                for (int j = kk >> 1; j > 0; j >>= 1) {
                    bool grp0 = (((2 * tw) & kk) == 0);    // same for both slots
                    if (j == 1) {
                        ull mxv = umax64(O0, O1), mnv = umin64(O0, O1);
                        O0 = grp0 ? mxv : mnv;
                        O1 = grp0 ? mnv : mxv;
                    } else {
                        int jh = j >> 1;
                        ull b0 = __shfl_xor_sync(0xffffffffu, O0, jh);
                        ull b1 = __shfl_xor_sync(0xffffffffu, O1, jh);
                        bool mx = (((tw & jh) == 0) == grp0);
                        O0 = mx ? umax64(O0, b0) : umin64(O0, b0);
                        O1 = mx ? umax64(O1, b1) : umin64(O1, b1);
                    }
                }
            }

            // reverse odds: O_rev[2t] = O[2(31-t)+1], O_rev[2t+1] = O[2(31-t)]
            ull rev0 = __shfl_sync(0xffffffffu, O1, 31 - tw);
            ull rev1 = __shfl_sync(0xffffffffu, O0, 31 - tw);

            // evens: re-index (parent rank p -> expanded idx 2p), then combine
            E0 = (E0 & ~0xFFull) | (ull)(127 - 4 * tw);
            E1 = (E1 & ~0xFFull) | (ull)(127 - (4 * tw + 2));
            E0 = umax64(E0, rev0);   // top-64 multiset, bitonic sequence
            E1 = umax64(E1, rev1);

            // 6-stage desc merge -> sorted. Final level: skip (set-invariant
            // epilogue, validated in R6/R7).
            if (it < 6) {
                #pragma unroll
                for (int j = 32; j > 0; j >>= 1) {
                    if (j == 1) {
                        ull mxv = umax64(E0, E1), mnv = umin64(E0, E1);
                        E0 = mxv; E1 = mnv;
                    } else {
                        int jh = j >> 1;
                        ull b0 = __shfl_xor_sync(0xffffffffu, E0, jh);
                        ull b1 = __shfl_xor_sync(0xffffffffu, E1, jh);
                        bool mx = ((tw & jh) == 0);
                        E0 = mx ? umax64(E0, b0) : umin64(E0, b0);
                        E1 = mx ? umax64(E1, b1) : umin64(E1, b1);
                    }
                }
            }

            // decode next-level parents (reads before writes, then syncwarp)
            int e0 = 127 - (int)(E0 & 0xFFu);
            int e1 = 127 - (int)(E1 & 0xFFu);
            int zs0 = 2 * zpar[e0 >> 1] + (e0 & 1);
            int zs1 = 2 * zpar[e1 >> 1] + (e1 & 1);
            __syncwarp();
            zpar[2 * tw]     = zs0;
            zpar[2 * tw + 1] = zs1;
            if (it == 6) { xkey[2 * tw] = E0; xkey[2 * tw + 1] = E1; }
        }
        __syncthreads();   // publish zpar (and xkey at it6) to warp 1
    }

    // ---------------- final attention over the 64 kept candidates ------------
    {
        key  = xkey[g];
        zsel = zpar[g];
        const float rf = tsrc * (1.0f / 2048.0f);
        int pos = min((int)rintf((float)zsel * rf), SS - 1);
        bool valid = ((float)pos < tsrc);
        float score = dec_score(key);
        float a = valid ? score * 0.125f : -1e9f;   // 1/sqrt(64)

        float m = a;
        m = fmaxf(m, __shfl_xor_sync(0xffffffffu, m, 16));
        m = fmaxf(m, __shfl_xor_sync(0xffffffffu, m, 8));
        m = fmaxf(m, __shfl_xor_sync(0xffffffffu, m, 4));
        m = fmaxf(m, __shfl_xor_sync(0xffffffffu, m, 2));
        m = fmaxf(m, __shfl_xor_sync(0xffffffffu, m, 1));
        if (lane == 0) red[g >> 5] = m;
        __syncthreads();
        m = fmaxf(red[0], red[1]);

        float e = valid ? expf(a - m) : 0.0f;   // invalid: ref exp underflows to 0
        float s = e;
        s += __shfl_xor_sync(0xffffffffu, s, 16);
        s += __shfl_xor_sync(0xffffffffu, s, 8);
        s += __shfl_xor_sync(0xffffffffu, s, 4);
        s += __shfl_xor_sync(0xffffffffu, s, 2);
        s += __shfl_xor_sync(0xffffffffu, s, 1);
        if (lane == 0) red[2 + (g >> 5)] = s;
        __syncthreads();
        s = red[2] + red[3];

        pvec[g]  = (s > 0.0f) ? (e / s) : 0.0f;  // all-invalid -> 0, matches ref
        pos_s[g] = pos;
        __syncthreads();

        // out[h] = sum_k p[k] * V[n, pos[k], h] ; thread g = h, coalesced loads
        const float* vb = v + (size_t)n * SS * HH + g;
        float acc = 0.0f;
        #pragma unroll 8
        for (int kk = 0; kk < KSEL; ++kk)
            acc = fmaf(pvec[kk], vb[(size_t)pos_s[kk] * HH], acc);
        out[((size_t)(n * TT + t)) * HH + g] = acc;
    }
    #undef SCORE_FRESH
}

extern "C" void kernel_launch(void* const* d_in, const int* in_sizes, int n_in,
                              void* d_out, int out_size)
{
    const float* q = (const float*)d_in[0];
    const float* k = (const float*)d_in[1];
    const float* v = (const float*)d_in[2];
    float* out = (float*)d_out;
    (void)in_sizes; (void)n_in; (void)out_size;

    tree_attn_kernel<<<NBATCH * TT, 64>>>(q, k, v, out);
}

// round 10
// speedup vs baseline: 1.3380x; 1.3380x over previous
#include <cuda_runtime.h>
#include <stdint.h>

#define NBATCH 16
#define TT     2048
#define SS     2048
#define HH     64

typedef unsigned long long ull;

__device__ __forceinline__ ull umax64(ull a, ull b) { return a > b ? a : b; }
__device__ __forceinline__ ull umin64(ull a, ull b) { return a < b ? a : b; }

// key = (sortable_score << 8) | (127 - expanded_idx); numeric DESC order ==
// desc by score, ties by ascending index (replicates lax.top_k exactly,
// given equal pos -> bit-equal score).
__device__ __forceinline__ ull enc_key(float s, int idx) {
    unsigned u  = __float_as_uint(s);
    unsigned su = (u & 0x80000000u) ? ~u : (u | 0x80000000u);
    return ((ull)su << 8) | (ull)(127 - idx);
}
__device__ __forceinline__ float dec_score(ull k) {
    unsigned su = (unsigned)(k >> 8);
    unsigned u  = (su & 0x80000000u) ? (su & 0x7FFFFFFFu) : ~su;
    return __uint_as_float(u);
}

__global__ __launch_bounds__(128, 16)
void tree_attn_kernel(const float* __restrict__ q,
                      const float* __restrict__ kmat,
                      const float* __restrict__ v,
                      float* __restrict__ out)
{
    // per-warp private scratch (one row per warp; NO block barriers anywhere)
    __shared__ float              sc_s[4][64];
    __shared__ int                zpar_s[4][64];
    __shared__ int                posb_s[4][64];
    __shared__ __align__(16) ull  pk_s[4][64];

    const int wid  = threadIdx.x >> 5;
    const int lane = threadIdx.x & 31;
    const int row  = blockIdx.x * 4 + wid;
    const int n    = row >> 11;
    const int t    = row & (TT - 1);
    const float tsrc = (float)(t + 1);
    const int l16  = lane & 15;
    const int hw   = lane >> 4;          // half-warp 0/1
    const unsigned FULL = 0xffffffffu;

    float* scw   = sc_s[wid];
    int*   zparw = zpar_s[wid];
    int*   posbw = posb_s[wid];
    ull*   pkw   = pk_s[wid];

    const float* kbase = kmat + (size_t)n * SS * HH;
    const float4 q4 = ((const float4*)(q + ((size_t)(n * TT + t)) * HH))[l16];

    // R3-verbatim pinned scoring tree (bit-matches the reference einsum;
    // the reduction order must NOT change). 2 candidates per warp pass.
    #define SCORE2(PP, J)                                                     \
        {                                                                     \
            const float4* krow = (const float4*)(kbase + (size_t)(PP) * HH);  \
            float4 k4 = krow[l16];                                            \
            float part = q4.x * k4.x + q4.y * k4.y + q4.z * k4.z + q4.w * k4.w;\
            part += __shfl_xor_sync(FULL, part, 1);                           \
            part += __shfl_xor_sync(FULL, part, 2);                           \
            part += __shfl_xor_sync(FULL, part, 4);                           \
            part += __shfl_xor_sync(FULL, part, 8);                           \
            if (l16 == 0) scw[2 * (J) + hw] = part;                           \
        }

    // ------------- it0: 32 fresh candidates (z = c), w2 = 32 ----------------
    ull key;
    {
        const float r = tsrc * (1.0f / 32.0f);
        #pragma unroll
        for (int j = 0; j < 16; ++j) {
            int c  = 2 * j + hw;
            int pp = min((int)rintf((float)c * r), SS - 1);
            SCORE2(pp, j)
        }
        __syncwarp();
        key = enc_key(scw[lane], lane);      // idx == z at level 0
        #pragma unroll
        for (int kk = 2; kk <= 32; kk <<= 1)
            #pragma unroll
            for (int j2 = kk >> 1; j2 > 0; j2 >>= 1) {
                ull p = __shfl_xor_sync(FULL, key, j2);
                bool mx = (((lane & j2) == 0) == ((lane & kk) == 0));
                key = mx ? umax64(key, p) : umin64(key, p);
            }
    }

    // 2-packed state: E0/E1 = kept keys at slots 2t/2t+1; zp0/zp1 parent z.
    // it0 kept 32 -> pad slots 32..63 with key 0 (below any real key).
    ull E0, E1; int zp0, zp1;
    {
        ull k0 = __shfl_sync(FULL, key, (2 * lane) & 31);
        ull k1 = __shfl_sync(FULL, key, (2 * lane + 1) & 31);
        bool lo = lane < 16;
        E0 = lo ? k0 : 0ull;
        E1 = lo ? k1 : 0ull;
        zp0 = lo ? (127 - (int)(k0 & 0xFF)) : 0;
        zp1 = lo ? (127 - (int)(k1 & 0xFF)) : 0;
    }

    // ------------- levels it = 1..6 (it1: 32 parents, else 64) --------------
    #pragma unroll 1
    for (int it = 1; it < 7; ++it) {
        const int   nPar = (it == 1) ? 32 : 64;
        const float r    = tsrc / (float)(32 << it);

        // precompute per lane (parent ranks 2t, 2t+1): odd/even child pos.
        // collision skip: posO == posE -> odd child's fresh score would be
        // bit-equal to the parent's -> inherit it, skip LDG+SHFL.
        int pE0 = min((int)rintf((float)(2 * zp0) * r),     SS - 1);
        int pO0 = min((int)rintf((float)(2 * zp0 + 1) * r), SS - 1);
        int pE1 = min((int)rintf((float)(2 * zp1) * r),     SS - 1);
        int pO1 = min((int)rintf((float)(2 * zp1 + 1) * r), SS - 1);
        bool real0 = (2 * lane)     < nPar;
        bool real1 = (2 * lane + 1) < nPar;
        bool skipPair = (!real1) || (pO0 == pE0 && pO1 == pE1);

        *(int2*)(zparw + 2 * lane) = make_int2(zp0, zp1);
        *(int2*)(posbw + 2 * lane) = make_int2(pO0, pO1);
        if (skipPair && real0) {
            *(float2*)(scw + 2 * lane) =
                make_float2(dec_score(E0), dec_score(E1));
        }
        unsigned fresh = ~__ballot_sync(FULL, skipPair);
        __syncwarp();

        // fresh odd-children passes (warp-uniform branch per pass)
        for (int j = 0; j < nPar / 2; ++j) {
            if ((fresh >> j) & 1u) {
                int pp = posbw[2 * j + hw];
                SCORE2(pp, j)
            }
        }
        __syncwarp();

        // odd keys 2/lane (expanded idx = 2*rank+1); pads -> 0
        ull O0 = real0 ? enc_key(scw[2 * lane],     4 * lane + 1) : 0ull;
        ull O1 = real1 ? enc_key(scw[2 * lane + 1], 4 * lane + 3) : 0ull;

        // desc bitonic sort of 64 odds, 2/lane (R8-validated network)
        #pragma unroll
        for (int kk = 2; kk <= 64; kk <<= 1) {
            #pragma unroll
            for (int j2 = kk >> 1; j2 > 0; j2 >>= 1) {
                bool grp0 = (((2 * lane) & kk) == 0);
                if (j2 == 1) {
                    ull mxv = umax64(O0, O1), mnv = umin64(O0, O1);
                    O0 = grp0 ? mxv : mnv;
                    O1 = grp0 ? mnv : mxv;
                } else {
                    int jh = j2 >> 1;
                    ull b0 = __shfl_xor_sync(FULL, O0, jh);
                    ull b1 = __shfl_xor_sync(FULL, O1, jh);
                    bool mx = (((lane & jh) == 0) == grp0);
                    O0 = mx ? umax64(O0, b0) : umin64(O0, b0);
                    O1 = mx ? umax64(O1, b1) : umin64(O1, b1);
                }
            }
        }

        // combine: evens (sorted, reindexed to idx 2*slot) vs reversed odds
        ull rev0 = __shfl_sync(FULL, O1, 31 - lane);
        ull rev1 = __shfl_sync(FULL, O0, 31 - lane);
        E0 = (E0 & ~0xFFull) | (ull)(127 - 4 * lane);
        E1 = (E1 & ~0xFFull) | (ull)(127 - (4 * lane + 2));
        E0 = umax64(E0, rev0);              // top-64 multiset, bitonic
        E1 = umax64(E1, rev1);

        // 6-stage desc merge -> sorted (skipped at final level: epilogue is
        // set-order invariant — validated R6/R8)
        if (it < 6) {
            #pragma unroll
            for (int j2 = 32; j2 > 1; j2 >>= 1) {
                int jh = j2 >> 1;
                ull b0 = __shfl_xor_sync(FULL, E0, jh);
                ull b1 = __shfl_xor_sync(FULL, E1, jh);
                bool mx = ((lane & jh) == 0);
                E0 = mx ? umax64(E0, b0) : umin64(E0, b0);
                E1 = mx ? umax64(E1, b1) : umin64(E1, b1);
            }
            ull mxv = umax64(E0, E1), mnv = umin64(E0, E1);
            E0 = mxv; E1 = mnv;
        }

        // decode next-level parents (zparw stable during this level)
        int e0 = 127 - (int)(E0 & 0xFF);
        int e1 = 127 - (int)(E1 & 0xFF);
        zp0 = 2 * zparw[e0 >> 1] + (e0 & 1);
        zp1 = 2 * zparw[e1 >> 1] + (e1 & 1);
    }

    // ------------- final attention over the 64 kept (warp-local) ------------
    {
        const float rf = tsrc * (1.0f / 2048.0f);
        int pos0 = min((int)rintf((float)zp0 * rf), SS - 1);
        int pos1 = min((int)rintf((float)zp1 * rf), SS - 1);
        bool v0 = ((float)pos0 < tsrc);
        bool v1 = ((float)pos1 < tsrc);
        float a0 = v0 ? dec_score(E0) * 0.125f : -1e9f;   // 1/sqrt(64)
        float a1 = v1 ? dec_score(E1) * 0.125f : -1e9f;

        float m = fmaxf(a0, a1);
        m = fmaxf(m, __shfl_xor_sync(FULL, m, 16));
        m = fmaxf(m, __shfl_xor_sync(FULL, m, 8));
        m = fmaxf(m, __shfl_xor_sync(FULL, m, 4));
        m = fmaxf(m, __shfl_xor_sync(FULL, m, 2));
        m = fmaxf(m, __shfl_xor_sync(FULL, m, 1));

        float e0 = v0 ? expf(a0 - m) : 0.0f;   // invalid: ref underflows to 0
        float e1 = v1 ? expf(a1 - m) : 0.0f;
        float s = e0 + e1;
        s += __shfl_xor_sync(FULL, s, 16);
        s += __shfl_xor_sync(FULL, s, 8);
        s += __shfl_xor_sync(FULL, s, 4);
        s += __shfl_xor_sync(FULL, s, 2);
        s += __shfl_xor_sync(FULL, s, 1);

        float p0 = (s > 0.0f) ? (e0 / s) : 0.0f;  // all-invalid -> 0 (ref)
        float p1 = (s > 0.0f) ? (e1 / s) : 0.0f;

        // pack (pos, p) per slot, then warp-coalesced V gather
        pkw[2 * lane]     = ((ull)(unsigned)pos0 << 32) | __float_as_uint(p0);
        pkw[2 * lane + 1] = ((ull)(unsigned)pos1 << 32) | __float_as_uint(p1);
        __syncwarp();

        const float* vb = v + (size_t)n * SS * HH;
        float acc0 = 0.0f, acc1 = 0.0f;
        #pragma unroll 8
        for (int kk = 0; kk < 64; ++kk) {
            ull pv = pkw[kk];
            int pos = (int)(pv >> 32);
            float p = __uint_as_float((unsigned)pv);
            float2 v2 = *(const float2*)(vb + (size_t)pos * HH + 2 * lane);
            acc0 = fmaf(p, v2.x, acc0);
            acc1 = fmaf(p, v2.y, acc1);
        }
        ((float2*)(out + ((size_t)(n * TT + t)) * HH))[lane] =
            make_float2(acc0, acc1);
    }
    #undef SCORE2
}

extern "C" void kernel_launch(void* const* d_in, const int* in_sizes, int n_in,
                              void* d_out, int out_size)
{
    const float* q = (const float*)d_in[0];
    const float* k = (const float*)d_in[1];
    const float* v = (const float*)d_in[2];
    float* out = (float*)d_out;
    (void)in_sizes; (void)n_in; (void)out_size;

    tree_attn_kernel<<<(NBATCH * TT) / 4, 128>>>(q, k, v, out);
}

// round 11
// speedup vs baseline: 1.4263x; 1.0659x over previous
#include <cuda_runtime.h>
#include <stdint.h>

#define NBATCH 16
#define TT     2048
#define SS     2048
#define HH     64

typedef unsigned long long ull;

__device__ __forceinline__ ull umax64(ull a, ull b) { return a > b ? a : b; }
__device__ __forceinline__ ull umin64(ull a, ull b) { return a < b ? a : b; }

// key = (sortable_score << 8) | (127 - expanded_idx); numeric DESC order ==
// desc by score, ties by ascending index (replicates lax.top_k exactly,
// given equal pos -> bit-equal score).
__device__ __forceinline__ ull enc_key(float s, int idx) {
    unsigned u  = __float_as_uint(s);
    unsigned su = (u & 0x80000000u) ? ~u : (u | 0x80000000u);
    return ((ull)su << 8) | (ull)(127 - idx);
}
__device__ __forceinline__ float dec_score(ull k) {
    unsigned su = (unsigned)(k >> 8);
    unsigned u  = (su & 0x80000000u) ? (su & 0x7FFFFFFFu) : ~su;
    return __uint_as_float(u);
}

__global__ __launch_bounds__(128, 16)
void tree_attn_kernel(const float* __restrict__ q,
                      const float* __restrict__ kmat,
                      const float* __restrict__ v,
                      float* __restrict__ out)
{
    // per-warp private scratch (one row per warp; NO block barriers anywhere)
    __shared__ float              sc_s[4][66];   // scores by child slot (+pad)
    __shared__ int                zpar_s[4][64]; // parent z values
    __shared__ __align__(8) int2  fl_s[4][66];   // compacted fresh list (+pad)
    __shared__ __align__(16) ull  pk_s[4][64];   // epilogue (pos,p) packs

    const int wid  = threadIdx.x >> 5;
    const int lane = threadIdx.x & 31;
    const int row  = blockIdx.x * 4 + wid;
    const int n    = row >> 11;
    const int t    = row & (TT - 1);
    const float tsrc = (float)(t + 1);
    const int l16  = lane & 15;
    const int hw   = lane >> 4;          // half-warp 0/1
    const unsigned FULL = 0xffffffffu;
    const unsigned LT   = (1u << lane) - 1u;

    float* scw   = sc_s[wid];
    int*   zparw = zpar_s[wid];
    int2*  flw   = fl_s[wid];
    ull*   pkw   = pk_s[wid];

    const float* kbase = kmat + (size_t)n * SS * HH;
    const float4 q4 = ((const float4*)(q + ((size_t)(n * TT + t)) * HH))[l16];

    // R3-verbatim pinned scoring tree (bit-matches the reference einsum;
    // the reduction order must NOT change). 2 candidates per warp pass.
    #define SCORE2(PP, SLOT)                                                  \
        {                                                                     \
            const float4* krow = (const float4*)(kbase + (size_t)(PP) * HH);  \
            float4 k4 = krow[l16];                                            \
            float part = q4.x * k4.x + q4.y * k4.y + q4.z * k4.z + q4.w * k4.w;\
            part += __shfl_xor_sync(FULL, part, 1);                           \
            part += __shfl_xor_sync(FULL, part, 2);                           \
            part += __shfl_xor_sync(FULL, part, 4);                           \
            part += __shfl_xor_sync(FULL, part, 8);                           \
            if (l16 == 0) scw[SLOT] = part;                                   \
        }

    // ------------- it0: 32 fresh candidates (z = c), w2 = 32 ----------------
    ull key;
    {
        const float r = tsrc * (1.0f / 32.0f);
        #pragma unroll
        for (int j = 0; j < 16; ++j) {
            int c  = 2 * j + hw;
            int pp = min((int)rintf((float)c * r), SS - 1);
            SCORE2(pp, c)
        }
        __syncwarp();
        key = enc_key(scw[lane], lane);      // idx == z at level 0
        #pragma unroll
        for (int kk = 2; kk <= 32; kk <<= 1)
            #pragma unroll
            for (int j2 = kk >> 1; j2 > 0; j2 >>= 1) {
                ull p = __shfl_xor_sync(FULL, key, j2);
                bool mx = (((lane & j2) == 0) == ((lane & kk) == 0));
                key = mx ? umax64(key, p) : umin64(key, p);
            }
    }

    // 2-packed state: E0/E1 = kept keys at slots 2t/2t+1; zp0/zp1 parent z.
    // it0 kept 32 -> pad slots 32..63 with key 0 (below any real key).
    ull E0, E1; int zp0, zp1;
    {
        ull k0 = __shfl_sync(FULL, key, (2 * lane) & 31);
        ull k1 = __shfl_sync(FULL, key, (2 * lane + 1) & 31);
        bool lo = lane < 16;
        E0 = lo ? k0 : 0ull;
        E1 = lo ? k1 : 0ull;
        zp0 = lo ? (127 - (int)(k0 & 0xFF)) : 0;
        zp1 = lo ? (127 - (int)(k1 & 0xFF)) : 0;
    }

    // ------------- levels it = 1..6 (it1: 32 parents, else 64) --------------
    #pragma unroll 1
    for (int it = 1; it < 7; ++it) {
        const int   nPar = (it == 1) ? 32 : 64;
        const float r    = tsrc / (float)(32 << it);
        const int   a0   = 2 * lane, a1 = 2 * lane + 1;   // parent ranks

        // per-candidate collision skip: odd child landing on the even
        // sibling's token has a score bit-equal to the parent's -> inherit.
        int pE0 = min((int)rintf((float)(2 * zp0) * r),     SS - 1);
        int pO0 = min((int)rintf((float)(2 * zp0 + 1) * r), SS - 1);
        int pE1 = min((int)rintf((float)(2 * zp1) * r),     SS - 1);
        int pO1 = min((int)rintf((float)(2 * zp1 + 1) * r), SS - 1);
        bool real0 = a0 < nPar;
        bool real1 = a1 < nPar;
        bool fresh0 = real0 && (pO0 != pE0);
        bool fresh1 = real1 && (pO1 != pE1);

        if (real0 && !fresh0) scw[a0] = dec_score(E0);
        if (real1 && !fresh1) scw[a1] = dec_score(E1);
        *(int2*)(zparw + a0) = make_int2(zp0, zp1);

        // compact fresh candidates into a dense worklist (pos, slot)
        unsigned m0 = __ballot_sync(FULL, fresh0);
        unsigned m1 = __ballot_sync(FULL, fresh1);
        int c0 = __popc(m0);
        int nF = c0 + __popc(m1);
        if (fresh0) flw[__popc(m0 & LT)]      = make_int2(pO0, a0);
        if (fresh1) flw[c0 + __popc(m1 & LT)] = make_int2(pO1, a1);
        if (lane == 0) flw[nF] = make_int2(0, 64);   // pad entry -> scw[64]
        __syncwarp();

        // uniform scoring passes over the compacted list (2 per pass)
        for (int j = 0; j < nF; j += 2) {
            int2 ent = flw[j + hw];
            SCORE2(ent.x, ent.y)
        }
        __syncwarp();

        // odd keys 2/lane (expanded idx = 2*rank+1); pads -> 0
        ull O0 = real0 ? enc_key(scw[a0], 2 * a0 + 1) : 0ull;
        ull O1 = real1 ? enc_key(scw[a1], 2 * a1 + 1) : 0ull;

        // desc bitonic sort of 64 odds, 2/lane (R8/R9-validated network)
        #pragma unroll
        for (int kk = 2; kk <= 64; kk <<= 1) {
            #pragma unroll
            for (int j2 = kk >> 1; j2 > 0; j2 >>= 1) {
                bool grp0 = ((a0 & kk) == 0);
                if (j2 == 1) {
                    ull mxv = umax64(O0, O1), mnv = umin64(O0, O1);
                    O0 = grp0 ? mxv : mnv;
                    O1 = grp0 ? mnv : mxv;
                } else {
                    int jh = j2 >> 1;
                    ull b0 = __shfl_xor_sync(FULL, O0, jh);
                    ull b1 = __shfl_xor_sync(FULL, O1, jh);
                    bool mx = (((lane & jh) == 0) == grp0);
                    O0 = mx ? umax64(O0, b0) : umin64(O0, b0);
                    O1 = mx ? umax64(O1, b1) : umin64(O1, b1);
                }
            }
        }

        // combine: evens (sorted, reindexed to idx 2*slot) vs reversed odds
        ull rev0 = __shfl_sync(FULL, O1, 31 - lane);
        ull rev1 = __shfl_sync(FULL, O0, 31 - lane);
        E0 = (E0 & ~0xFFull) | (ull)(127 - 4 * lane);
        E1 = (E1 & ~0xFFull) | (ull)(127 - (4 * lane + 2));
        E0 = umax64(E0, rev0);              // top-64 multiset, bitonic
        E1 = umax64(E1, rev1);

        // 6-stage desc merge -> sorted (skipped at final level: epilogue is
        // set-order invariant — validated R6/R8/R9)
        if (it < 6) {
            #pragma unroll
            for (int j2 = 32; j2 > 1; j2 >>= 1) {
                int jh = j2 >> 1;
                ull b0 = __shfl_xor_sync(FULL, E0, jh);
                ull b1 = __shfl_xor_sync(FULL, E1, jh);
                bool mx = ((lane & jh) == 0);
                E0 = mx ? umax64(E0, b0) : umin64(E0, b0);
                E1 = mx ? umax64(E1, b1) : umin64(E1, b1);
            }
            ull mxv = umax64(E0, E1), mnv = umin64(E0, E1);
            E0 = mxv; E1 = mnv;
        }

        // decode next-level parents (zparw stable during this level)
        int e0 = 127 - (int)(E0 & 0xFF);
        int e1 = 127 - (int)(E1 & 0xFF);
        zp0 = 2 * zparw[e0 >> 1] + (e0 & 1);
        zp1 = 2 * zparw[e1 >> 1] + (e1 & 1);
    }

    // ------------- final attention over the 64 kept (warp-local) ------------
    {
        const float rf = tsrc * (1.0f / 2048.0f);
        int pos0 = min((int)rintf((float)zp0 * rf), SS - 1);
        int pos1 = min((int)rintf((float)zp1 * rf), SS - 1);
        bool v0 = ((float)pos0 < tsrc);
        bool v1 = ((float)pos1 < tsrc);
        float a0 = v0 ? dec_score(E0) * 0.125f : -1e9f;   // 1/sqrt(64)
        float a1 = v1 ? dec_score(E1) * 0.125f : -1e9f;

        float m = fmaxf(a0, a1);
        m = fmaxf(m, __shfl_xor_sync(FULL, m, 16));
        m = fmaxf(m, __shfl_xor_sync(FULL, m, 8));
        m = fmaxf(m, __shfl_xor_sync(FULL, m, 4));
        m = fmaxf(m, __shfl_xor_sync(FULL, m, 2));
        m = fmaxf(m, __shfl_xor_sync(FULL, m, 1));

        float e0 = v0 ? expf(a0 - m) : 0.0f;   // invalid: ref underflows to 0
        float e1 = v1 ? expf(a1 - m) : 0.0f;
        float s = e0 + e1;
        s += __shfl_xor_sync(FULL, s, 16);
        s += __shfl_xor_sync(FULL, s, 8);
        s += __shfl_xor_sync(FULL, s, 4);
        s += __shfl_xor_sync(FULL, s, 2);
        s += __shfl_xor_sync(FULL, s, 1);

        float p0 = (s > 0.0f) ? (e0 / s) : 0.0f;  // all-invalid -> 0 (ref)
        float p1 = (s > 0.0f) ? (e1 / s) : 0.0f;

        // pack (pos, p) per slot, then warp-coalesced V gather
        pkw[2 * lane]     = ((ull)(unsigned)pos0 << 32) | __float_as_uint(p0);
        pkw[2 * lane + 1] = ((ull)(unsigned)pos1 << 32) | __float_as_uint(p1);
        __syncwarp();

        const float* vb = v + (size_t)n * SS * HH;
        float acc0 = 0.0f, acc1 = 0.0f;
        #pragma unroll 4
        for (int kk = 0; kk < 32; ++kk) {
            uint4 u = ((const uint4*)pkw)[kk];     // 2 packed entries
            float pa  = __uint_as_float(u.x);
            int   psa = (int)u.y;
            float pb  = __uint_as_float(u.z);
            int   psb = (int)u.w;
            float2 va = *(const float2*)(vb + (size_t)psa * HH + 2 * lane);
            acc0 = fmaf(pa, va.x, acc0);
            acc1 = fmaf(pa, va.y, acc1);
            float2 vbv = *(const float2*)(vb + (size_t)psb * HH + 2 * lane);
            acc0 = fmaf(pb, vbv.x, acc0);
            acc1 = fmaf(pb, vbv.y, acc1);
        }
        ((float2*)(out + ((size_t)(n * TT + t)) * HH))[lane] =
            make_float2(acc0, acc1);
    }
    #undef SCORE2
}

extern "C" void kernel_launch(void* const* d_in, const int* in_sizes, int n_in,
                              void* d_out, int out_size)
{
    const float* q = (const float*)d_in[0];
    const float* k = (const float*)d_in[1];
    const float* v = (const float*)d_in[2];
    float* out = (float*)d_out;
    (void)in_sizes; (void)n_in; (void)out_size;

    tree_attn_kernel<<<(NBATCH * TT) / 4, 128>>>(q, k, v, out);
}